// round 2
// baseline (speedup 1.0000x reference)
#include <cuda_runtime.h>
#include <cuda_bf16.h>

// Problem constants (LatentCoulombLongRange: N=8192, F=128, H=64, B=8)
#define MAXN 8192
#define FDIM 128
#define HDIM 64
#define MAXB 64

// Scratch (allocation-free rule: __device__ globals)
__device__ float  d_qraw[MAXN];
__device__ float4 d_qpos[MAXN];       // {x, y, z, centered q}
__device__ int    d_gstart[MAXB];
__device__ int    d_gend[MAXB];
__device__ float  d_gmean[MAXB];

// ---------------------------------------------------------------------------
// K1: charge-head MLP  q_raw[i] = (silu(x W1 + b1) W2 + b2)
//     one block (64 threads) per atom; also detects sorted-batch graph bounds.
// ---------------------------------------------------------------------------
__global__ void mlp_kernel(const float* __restrict__ x,
                           const float* __restrict__ W1,
                           const float* __restrict__ b1,
                           const float* __restrict__ W2,
                           const float* __restrict__ b2,
                           const int* __restrict__ batch,
                           int n) {
    int i = blockIdx.x;
    int h = threadIdx.x;                 // 0..63
    __shared__ float sx[FDIM];
    __shared__ float part[2];

    sx[h]      = x[i * FDIM + h];
    sx[h + 64] = x[i * FDIM + 64 + h];
    __syncthreads();

    float acc = b1[h];
#pragma unroll
    for (int f = 0; f < FDIM; f++)
        acc = fmaf(sx[f], W1[f * HDIM + h], acc);

    // SiLU
    float s = acc * __frcp_rn(1.0f + __expf(-acc));
    float v = s * W2[h];

    // reduce 64 values (2 warps)
#pragma unroll
    for (int off = 16; off; off >>= 1)
        v += __shfl_down_sync(0xffffffffu, v, off);
    if ((h & 31) == 0) part[h >> 5] = v;
    __syncthreads();

    if (h == 0) {
        d_qraw[i] = part[0] + part[1] + b2[0];
        // sorted-batch segment boundaries
        int g = batch[i];
        if (i == 0     || batch[i - 1] != g) d_gstart[g] = i;
        if (i == n - 1 || batch[i + 1] != g) d_gend[g]   = i + 1;
    }
}

// ---------------------------------------------------------------------------
// K2: per-graph mean charge (single block, run-length segmented sums)
// ---------------------------------------------------------------------------
__global__ void mean_kernel(const int* __restrict__ batch, int n, int nb) {
    __shared__ float ssum[MAXB];
    __shared__ int   scnt[MAXB];
    int t = threadIdx.x;                 // 256 threads
    if (t < nb) { ssum[t] = 0.0f; scnt[t] = 0; }
    __syncthreads();

    int per = (n + blockDim.x - 1) / blockDim.x;
    int i0 = t * per;
    int i1 = min(n, i0 + per);
    if (i0 < i1) {
        int cg = batch[i0];
        float s = 0.0f; int c = 0;
        for (int i = i0; i < i1; i++) {
            int g = batch[i];
            if (g != cg) {
                atomicAdd(&ssum[cg], s); atomicAdd(&scnt[cg], c);
                s = 0.0f; c = 0; cg = g;
            }
            s += d_qraw[i]; c++;
        }
        atomicAdd(&ssum[cg], s); atomicAdd(&scnt[cg], c);
    }
    __syncthreads();
    if (t < nb)
        d_gmean[t] = ssum[t] / fmaxf(1.0f, (float)scnt[t]);
}

// ---------------------------------------------------------------------------
// K3: pack {pos, centered q} into float4 for 1-LDG.128-per-pair inner loop
// ---------------------------------------------------------------------------
__global__ void pack_kernel(const float* __restrict__ pos,
                            const int* __restrict__ batch, int n) {
    int i = blockIdx.x * blockDim.x + threadIdx.x;
    if (i < n) {
        float qc = d_qraw[i] - d_gmean[batch[i]];
        d_qpos[i] = make_float4(pos[3 * i], pos[3 * i + 1], pos[3 * i + 2], qc);
    }
}

// ---------------------------------------------------------------------------
// K4: screened Coulomb pair sum. One warp per atom i; lanes stride over the
//     atom's (contiguous, sorted) graph range [gs, ge).
//     out[i] = 0.5 * q_i * sum_{j in graph, j != i} q_j * exp(-scr*r)/r
// ---------------------------------------------------------------------------
__global__ void pair_kernel(const int* __restrict__ batch,
                            const float* __restrict__ scr_p,
                            const float* __restrict__ soft_p,
                            float* __restrict__ out, int n) {
    int warp = (blockIdx.x * blockDim.x + threadIdx.x) >> 5;
    int lane = threadIdx.x & 31;
    if (warp >= n) return;
    int i = warp;

    float scr   = *scr_p;
    float soft  = *soft_p;
    float soft2 = soft * soft;

    int g  = batch[i];
    int gs = d_gstart[g];
    int ge = d_gend[g];

    float4 pi = d_qpos[i];
    float acc = 0.0f;

    for (int j = gs + lane; j < ge; j += 32) {
        float4 pj = d_qpos[j];
        float dx = pj.x - pi.x;
        float dy = pj.y - pi.y;
        float dz = pj.z - pi.z;
        float r2 = fmaf(dx, dx, fmaf(dy, dy, fmaf(dz, dz, soft2)));
        float rinv = rsqrtf(r2);
        float r = r2 * rinv;
        float k = __expf(-scr * r) * rinv;
        if (j != i) acc = fmaf(pj.w, k, acc);
    }

#pragma unroll
    for (int off = 16; off; off >>= 1)
        acc += __shfl_down_sync(0xffffffffu, acc, off);

    if (lane == 0) out[i] = 0.5f * pi.w * acc;
}

// ---------------------------------------------------------------------------
// launch
// inputs: 0:x 1:pos 2:cell 3:W1 4:b1 5:W2 6:b2 7:screening 8:softening 9:batch
// ---------------------------------------------------------------------------
extern "C" void kernel_launch(void* const* d_in, const int* in_sizes, int n_in,
                              void* d_out, int out_size) {
    const float* x     = (const float*)d_in[0];
    const float* pos   = (const float*)d_in[1];
    const float* W1    = (const float*)d_in[3];
    const float* b1    = (const float*)d_in[4];
    const float* W2    = (const float*)d_in[5];
    const float* b2    = (const float*)d_in[6];
    const float* scr   = (const float*)d_in[7];
    const float* soft  = (const float*)d_in[8];
    const int*   batch = (const int*)d_in[9];
    float* out = (float*)d_out;

    int n  = in_sizes[9];          // N atoms
    int nb = in_sizes[2] / 9;      // B graphs (cell is [B,3,3])

    mlp_kernel<<<n, HDIM>>>(x, W1, b1, W2, b2, batch, n);
    mean_kernel<<<1, 256>>>(batch, n, nb);
    pack_kernel<<<(n + 255) / 256, 256>>>(pos, batch, n);
    int threads = 256;
    int blocks  = (n * 32 + threads - 1) / threads;
    pair_kernel<<<blocks, threads>>>(batch, scr, soft, out, n);
}

// round 3
// speedup vs baseline: 1.0391x; 1.0391x over previous
#include <cuda_runtime.h>
#include <cuda_bf16.h>

// Problem constants (LatentCoulombLongRange: N=8192, F=128, H=64, B=8)
#define MAXN 8192
#define FDIM 128
#define HDIM 64
#define MAXB 64

// Scratch (allocation-free rule: __device__ globals)
__device__ float  d_qraw[MAXN];
__device__ float4 d_qpos[MAXN];       // {x, y, z, centered q}
__device__ int    d_gstart[MAXB];
__device__ int    d_gend[MAXB];
__device__ float  d_gmean[MAXB];

// ---------------------------------------------------------------------------
// K1: charge-head MLP  q_raw[i] = (silu(x W1 + b1) W2 + b2)
//     One warp (32 threads) per atom, 4 atoms per 128-thread block.
//     Each thread computes 2 hidden columns (h = 2*lane, 2*lane+1) via
//     float2 loads of W1 -> 4 issue slots per 2 columns instead of 6.
// ---------------------------------------------------------------------------
__global__ void mlp_kernel(const float* __restrict__ x,
                           const float* __restrict__ W1,
                           const float* __restrict__ b1,
                           const float* __restrict__ W2,
                           const float* __restrict__ b2,
                           const int* __restrict__ batch,
                           int n) {
    int sub  = threadIdx.x >> 5;           // atom sub-index in block (0..3)
    int lane = threadIdx.x & 31;
    int i = blockIdx.x * 4 + sub;
    if (i >= n) return;

    __shared__ float sx[4][FDIM];

    // warp loads its atom's x row: 32 lanes x float4 = 128 floats
    ((float4*)sx[sub])[lane] = ((const float4*)(x + i * FDIM))[lane];
    __syncwarp();

    const float2* W1v = (const float2*)W1;     // [128][32] float2
    float2 acc = ((const float2*)b1)[lane];

#pragma unroll
    for (int f = 0; f < FDIM; f++) {
        float  xf = sx[sub][f];
        float2 w  = W1v[f * 32 + lane];
        acc.x = fmaf(xf, w.x, acc.x);
        acc.y = fmaf(xf, w.y, acc.y);
    }

    // SiLU + W2 contraction (2 columns per thread)
    float2 w2 = ((const float2*)W2)[lane];
    float s0 = acc.x * __frcp_rn(1.0f + __expf(-acc.x));
    float s1 = acc.y * __frcp_rn(1.0f + __expf(-acc.y));
    float v = fmaf(s0, w2.x, s1 * w2.y);

#pragma unroll
    for (int off = 16; off; off >>= 1)
        v += __shfl_down_sync(0xffffffffu, v, off);

    if (lane == 0) {
        d_qraw[i] = v + b2[0];
        // sorted-batch segment boundaries
        int g = batch[i];
        if (i == 0     || batch[i - 1] != g) d_gstart[g] = i;
        if (i == n - 1 || batch[i + 1] != g) d_gend[g]   = i + 1;
    }
}

// ---------------------------------------------------------------------------
// K2: per-graph mean charge (single block, run-length segmented sums)
// ---------------------------------------------------------------------------
__global__ void mean_kernel(const int* __restrict__ batch, int n, int nb) {
    __shared__ float ssum[MAXB];
    __shared__ int   scnt[MAXB];
    int t = threadIdx.x;                 // 256 threads
    if (t < nb) { ssum[t] = 0.0f; scnt[t] = 0; }
    __syncthreads();

    int per = (n + blockDim.x - 1) / blockDim.x;
    int i0 = t * per;
    int i1 = min(n, i0 + per);
    if (i0 < i1) {
        int cg = batch[i0];
        float s = 0.0f; int c = 0;
        for (int i = i0; i < i1; i++) {
            int g = batch[i];
            if (g != cg) {
                atomicAdd(&ssum[cg], s); atomicAdd(&scnt[cg], c);
                s = 0.0f; c = 0; cg = g;
            }
            s += d_qraw[i]; c++;
        }
        atomicAdd(&ssum[cg], s); atomicAdd(&scnt[cg], c);
    }
    __syncthreads();
    if (t < nb)
        d_gmean[t] = ssum[t] / fmaxf(1.0f, (float)scnt[t]);
}

// ---------------------------------------------------------------------------
// K3: pack {pos, centered q} into float4 for 1-LDG.128-per-pair inner loop
// ---------------------------------------------------------------------------
__global__ void pack_kernel(const float* __restrict__ pos,
                            const int* __restrict__ batch, int n) {
    int i = blockIdx.x * blockDim.x + threadIdx.x;
    if (i < n) {
        float qc = d_qraw[i] - d_gmean[batch[i]];
        d_qpos[i] = make_float4(pos[3 * i], pos[3 * i + 1], pos[3 * i + 2], qc);
    }
}

// ---------------------------------------------------------------------------
// K4: screened Coulomb pair sum. One warp per atom i; lanes stride over the
//     atom's contiguous graph range [gs, ge), unrolled x4 for 4 independent
//     MUFU chains. Self-term (j==i) is included in the loop and subtracted
//     afterwards using the IDENTICAL intrinsic sequence so the approximation
//     error cancels exactly.
//     out[i] = 0.5 * q_i * sum_{j in graph, j != i} q_j * exp(-scr*r)/r
// ---------------------------------------------------------------------------
__device__ __forceinline__ float pair_term(float4 pj, float4 pi,
                                           float soft2, float nscr_log2e,
                                           float& k_out) {
    float dx = pj.x - pi.x;
    float dy = pj.y - pi.y;
    float dz = pj.z - pi.z;
    float r2 = fmaf(dx, dx, fmaf(dy, dy, fmaf(dz, dz, soft2)));
    float rinv = rsqrtf(r2);
    float r = r2 * rinv;
    k_out = exp2f(nscr_log2e * r) * rinv;
    return pj.w;
}

__global__ void pair_kernel(const int* __restrict__ batch,
                            const float* __restrict__ scr_p,
                            const float* __restrict__ soft_p,
                            float* __restrict__ out, int n) {
    int i    = (blockIdx.x * blockDim.x + threadIdx.x) >> 5;
    int lane = threadIdx.x & 31;
    if (i >= n) return;

    float scr   = *scr_p;
    float soft  = *soft_p;
    float soft2 = soft * soft;
    const float nscr_log2e = -scr * 1.44269504088896f;   // -scr * log2(e)

    int g  = batch[i];
    int gs = d_gstart[g];
    int ge = d_gend[g];

    float4 pi = d_qpos[i];
    float acc = 0.0f;

    int jlast = ge - 1;
    for (int j0 = gs + lane; j0 < ge; j0 += 128) {
        int j1 = j0 + 32, j2 = j0 + 64, j3 = j0 + 96;
        float4 p0 = d_qpos[min(j0, jlast)];
        float4 p1 = d_qpos[min(j1, jlast)];
        float4 p2 = d_qpos[min(j2, jlast)];
        float4 p3 = d_qpos[min(j3, jlast)];
        float k0, k1, k2, k3;
        float q0 = pair_term(p0, pi, soft2, nscr_log2e, k0);
        float q1 = pair_term(p1, pi, soft2, nscr_log2e, k1);
        float q2 = pair_term(p2, pi, soft2, nscr_log2e, k2);
        float q3 = pair_term(p3, pi, soft2, nscr_log2e, k3);
        // j0 < ge guaranteed by loop condition
        acc = fmaf(q0, k0, acc);
        if (j1 < ge) acc = fmaf(q1, k1, acc);
        if (j2 < ge) acc = fmaf(q2, k2, acc);
        if (j3 < ge) acc = fmaf(q3, k3, acc);
    }

    // subtract self-term computed with the same intrinsic sequence
    if (lane == 0) {
        float ks;
        float qs = pair_term(pi, pi, soft2, nscr_log2e, ks);
        acc -= qs * ks;
    }

#pragma unroll
    for (int off = 16; off; off >>= 1)
        acc += __shfl_down_sync(0xffffffffu, acc, off);

    if (lane == 0) out[i] = 0.5f * pi.w * acc;
}

// ---------------------------------------------------------------------------
// launch
// inputs: 0:x 1:pos 2:cell 3:W1 4:b1 5:W2 6:b2 7:screening 8:softening 9:batch
// ---------------------------------------------------------------------------
extern "C" void kernel_launch(void* const* d_in, const int* in_sizes, int n_in,
                              void* d_out, int out_size) {
    const float* x     = (const float*)d_in[0];
    const float* pos   = (const float*)d_in[1];
    const float* W1    = (const float*)d_in[3];
    const float* b1    = (const float*)d_in[4];
    const float* W2    = (const float*)d_in[5];
    const float* b2    = (const float*)d_in[6];
    const float* scr   = (const float*)d_in[7];
    const float* soft  = (const float*)d_in[8];
    const int*   batch = (const int*)d_in[9];
    float* out = (float*)d_out;

    int n  = in_sizes[9];          // N atoms
    int nb = in_sizes[2] / 9;      // B graphs (cell is [B,3,3])

    mlp_kernel<<<(n + 3) / 4, 128>>>(x, W1, b1, W2, b2, batch, n);
    mean_kernel<<<1, 256>>>(batch, n, nb);
    pack_kernel<<<(n + 255) / 256, 256>>>(pos, batch, n);
    int threads = 256;
    int blocks  = (n * 32 + threads - 1) / threads;
    pair_kernel<<<blocks, threads>>>(batch, scr, soft, out, n);
}